// round 7
// baseline (speedup 1.0000x reference)
#include <cuda_runtime.h>
#include <stdint.h>

#define BATCH 64
#define TT    512
#define HH    768
#define KK    4
#define ROWS  (BATCH*TT)   // 32768

// Scratch (no cudaMalloc allowed): ~1.2 MB total, L2-resident.
__device__ float4   g_emis[ROWS];          // [b*T + t] -> 4 emission logits
__device__ float4   g_scores[TT*BATCH];    // [t*64 + b] -> viterbi scores
__device__ unsigned g_hist[BATCH*TT];      // [b*512 + s] -> 4 backpointers (byte j = bp for tag j)
__device__ int      g_best[BATCH];

// ---------------------------------------------------------------------------
// K1: emissions[b,t,k] = sum_h sentences[b,t,h]*W[k,h] + bias[k]
// warp-per-row, W staged in shared, coalesced float4 loads, shuffle reduce.
// HBM-bound: 100.7 MB of `sent` at streaming rate.
// ---------------------------------------------------------------------------
__global__ __launch_bounds__(256) void k_emissions(
    const float* __restrict__ sent,   // [B,T,H]
    const float* __restrict__ W,      // [K,H]
    const float* __restrict__ bias)   // [K]
{
    __shared__ float4 sW[KK][HH/4];   // 12 KB
    __shared__ float  sb[KK];
    int tid = threadIdx.x;

    const float4* W4 = (const float4*)W;          // [K * H/4]
    for (int i = tid; i < KK*(HH/4); i += blockDim.x)
        sW[i/(HH/4)][i%(HH/4)] = W4[i];
    if (tid < KK) sb[tid] = bias[tid];
    __syncthreads();

    int warp = tid >> 5, lane = tid & 31;
    int row  = blockIdx.x * (blockDim.x >> 5) + warp;
    if (row >= ROWS) return;

    const float4* x = (const float4*)(sent + (size_t)row * HH);
    float a0 = 0.f, a1 = 0.f, a2 = 0.f, a3 = 0.f;
    #pragma unroll
    for (int i = 0; i < HH/128; i++) {            // 6 iterations
        int idx = i*32 + lane;
        float4 v  = x[idx];
        float4 w0 = sW[0][idx];
        float4 w1 = sW[1][idx];
        float4 w2 = sW[2][idx];
        float4 w3 = sW[3][idx];
        a0 += v.x*w0.x + v.y*w0.y + v.z*w0.z + v.w*w0.w;
        a1 += v.x*w1.x + v.y*w1.y + v.z*w1.z + v.w*w1.w;
        a2 += v.x*w2.x + v.y*w2.y + v.z*w2.z + v.w*w2.w;
        a3 += v.x*w3.x + v.y*w3.y + v.z*w3.z + v.w*w3.w;
    }
    #pragma unroll
    for (int d = 16; d; d >>= 1) {
        a0 += __shfl_xor_sync(0xffffffffu, a0, d);
        a1 += __shfl_xor_sync(0xffffffffu, a1, d);
        a2 += __shfl_xor_sync(0xffffffffu, a2, d);
        a3 += __shfl_xor_sync(0xffffffffu, a3, d);
    }
    if (lane == 0)
        g_emis[row] = make_float4(a0 + sb[0], a1 + sb[1], a2 + sb[2], a3 + sb[3]);
}

// ---------------------------------------------------------------------------
// K2: Viterbi forward scan. SIMT over batches: thread = batch, one 64-thread
// block. Stores all intermediate scores; bp recovery deferred to K3.
// ---------------------------------------------------------------------------
__global__ __launch_bounds__(64) void k_forward(
    const float* __restrict__ startT,
    const float* __restrict__ endT,
    const float* __restrict__ trans)   // [K,K], trans[i*4+j]
{
    int b = threadIdx.x;                     // 0..63

    float T00=__ldg(trans+ 0), T01=__ldg(trans+ 1), T02=__ldg(trans+ 2), T03=__ldg(trans+ 3);
    float T10=__ldg(trans+ 4), T11=__ldg(trans+ 5), T12=__ldg(trans+ 6), T13=__ldg(trans+ 7);
    float T20=__ldg(trans+ 8), T21=__ldg(trans+ 9), T22=__ldg(trans+10), T23=__ldg(trans+11);
    float T30=__ldg(trans+12), T31=__ldg(trans+13), T32=__ldg(trans+14), T33=__ldg(trans+15);

    const float4* em = g_emis + b * TT;
    float4 e0 = em[0];
    float s0 = __ldg(startT+0) + e0.x;
    float s1 = __ldg(startT+1) + e0.y;
    float s2 = __ldg(startT+2) + e0.z;
    float s3 = __ldg(startT+3) + e0.w;
    g_scores[0*BATCH + b] = make_float4(s0, s1, s2, s3);

    // 8-deep register prefetch ring (8 steps * ~64 cyc >> L2 latency)
    float4 buf[8];
    #pragma unroll
    for (int j = 0; j < 8; j++) buf[j] = em[1 + j];

    for (int base = 1; base < TT; base += 8) {
        #pragma unroll
        for (int j = 0; j < 8; j++) {
            int t = base + j;
            if (t < TT) {
                float4 e = buf[j];
                int tp = t + 8;
                buf[j] = (tp < TT) ? em[tp] : e;

                float c0, c1, c2, c3;
                float n0, n1, n2, n3;
                c0 = s0 + T00; c1 = s1 + T10; c2 = s2 + T20; c3 = s3 + T30;
                n0 = fmaxf(fmaxf(c0, c1), fmaxf(c2, c3)) + e.x;
                c0 = s0 + T01; c1 = s1 + T11; c2 = s2 + T21; c3 = s3 + T31;
                n1 = fmaxf(fmaxf(c0, c1), fmaxf(c2, c3)) + e.y;
                c0 = s0 + T02; c1 = s1 + T12; c2 = s2 + T22; c3 = s3 + T32;
                n2 = fmaxf(fmaxf(c0, c1), fmaxf(c2, c3)) + e.z;
                c0 = s0 + T03; c1 = s1 + T13; c2 = s2 + T23; c3 = s3 + T33;
                n3 = fmaxf(fmaxf(c0, c1), fmaxf(c2, c3)) + e.w;
                s0 = n0; s1 = n1; s2 = n2; s3 = n3;
                g_scores[t*BATCH + b] = make_float4(s0, s1, s2, s3);
            }
        }
    }

    float f0 = s0 + __ldg(endT+0);
    float f1 = s1 + __ldg(endT+1);
    float f2 = s2 + __ldg(endT+2);
    float f3 = s3 + __ldg(endT+3);
    int best = 0; float m = f0;                 // first-index tie-break (strict >)
    if (f1 > m) { m = f1; best = 1; }
    if (f2 > m) { m = f2; best = 2; }
    if (f3 > m) { m = f3; best = 3; }
    g_best[b] = best;
}

// ---------------------------------------------------------------------------
// K3: backpointer recovery, fully parallel over (step, batch).
// bp_s(j) = argmax_i ( scores[s][i] + trans[i][j] ), first-index wins.
// ---------------------------------------------------------------------------
__global__ __launch_bounds__(128) void k_bp(const float* __restrict__ trans)
{
    int idx = blockIdx.x * blockDim.x + threadIdx.x;
    if (idx >= (TT-1)*BATCH) return;
    int b = idx & (BATCH-1);
    int s = idx >> 6;                 // 0..510  (history index; step t = s+1)

    float4 sc = g_scores[s*BATCH + b];
    float tr[16];
    #pragma unroll
    for (int i = 0; i < 16; i++) tr[i] = __ldg(trans + i);

    unsigned h = 0;
    #pragma unroll
    for (int j = 0; j < 4; j++) {
        float c0 = sc.x + tr[0*4+j];
        float c1 = sc.y + tr[1*4+j];
        float c2 = sc.z + tr[2*4+j];
        float c3 = sc.w + tr[3*4+j];
        int bp = 0; float m = c0;
        if (c1 > m) { m = c1; bp = 1; }
        if (c2 > m) { m = c2; bp = 2; }
        if (c3 > m) { m = c3; bp = 3; }
        h |= (unsigned)bp << (8*j);
    }
    g_hist[b*TT + s] = h;
}

// ---------------------------------------------------------------------------
// K4: backtrack via PRMT chain. SIMT over batches (thread = batch),
// 8-chunk (32-step) register prefetch ring, packed float4 output stores.
// OUTPUT IS WRITTEN AS float32 (tags 0.0..3.0) — per H3: __output__ dtype
// is float32, int bit patterns read back as denormals => rel_err 1.0.
// ---------------------------------------------------------------------------
__global__ __launch_bounds__(64) void k_backtrack(float* __restrict__ out)
{
    int b = threadIdx.x;
    const unsigned* hb  = g_hist + b * TT;
    const uint4*    hb4 = (const uint4*)hb;
    float* ob = out + b * TT;

    int tag = g_best[b];
    ob[TT-1] = (float)tag;                           // k = 511

    // scalar leg: k = 510, 509, 508
    tag = __byte_perm(hb[510], 0, tag) & 3; ob[510] = (float)tag;
    tag = __byte_perm(hb[509], 0, tag) & 3; ob[509] = (float)tag;
    tag = __byte_perm(hb[508], 0, tag) & 3; ob[508] = (float)tag;

    // chunks c = 126 .. 0, chunk c covers k = 4c .. 4c+3
    uint4 buf[8];
    #pragma unroll
    for (int i = 0; i < 8; i++) buf[i] = hb4[126 - i];

    int c = 126;
    for (int blk = 0; blk < 16; blk++) {
        #pragma unroll
        for (int i = 0; i < 8; i++) {
            if (c >= 0) {
                uint4 h4 = buf[i];
                int pc = c - 8;
                if (pc >= 0) buf[i] = hb4[pc];       // prefetch 32 steps ahead
                int t3 = __byte_perm(h4.w, 0, tag) & 3;
                int t2 = __byte_perm(h4.z, 0, t3)  & 3;
                int t1 = __byte_perm(h4.y, 0, t2)  & 3;
                int t0 = __byte_perm(h4.x, 0, t1)  & 3;
                *(float4*)(ob + 4*c) =
                    make_float4((float)t0, (float)t1, (float)t2, (float)t3);
                tag = t0;
                c--;
            }
        }
    }
}

// ---------------------------------------------------------------------------
// Bind inputs BY ELEMENT COUNT (robust to input-order permutation).
// Distinct sizes: sentences 25165824, W 3072, transitions 16.
// The three 4-element vectors keep their relative order: b, start, end.
// ---------------------------------------------------------------------------
extern "C" void kernel_launch(void* const* d_in, const int* in_sizes, int n_in,
                              void* d_out, int out_size)
{
    const float* sent   = 0;
    const float* W      = 0;
    const float* bias   = 0;
    const float* startT = 0;
    const float* endT   = 0;
    const float* trans  = 0;

    int n4 = 0;  // count of 4-element vectors seen so far (order: b, start, end)
    for (int i = 0; i < n_in; i++) {
        int sz = in_sizes[i];
        const float* p = (const float*)d_in[i];
        if      (sz == BATCH*TT*HH) sent  = p;
        else if (sz == KK*HH)       W     = p;
        else if (sz == KK*KK)       trans = p;
        else if (sz == KK) {
            if      (n4 == 0) bias   = p;
            else if (n4 == 1) startT = p;
            else              endT   = p;
            n4++;
        }
    }
    float* out = (float*)d_out;                   // [64,512], __output__ = float32 (H3)

    k_emissions<<<ROWS/8, 256>>>(sent, W, bias);
    k_forward<<<1, 64>>>(startT, endT, trans);
    k_bp<<<((TT-1)*BATCH + 127)/128, 128>>>(trans);
    k_backtrack<<<1, 64>>>(out);
}

// round 8
// speedup vs baseline: 1.7796x; 1.7796x over previous
#include <cuda_runtime.h>
#include <stdint.h>

#define BATCH 64
#define TT    512
#define HH    768
#define KK    4
#define ROWS  (BATCH*TT)   // 32768
#define NCHUNK 32
#define CL     16          // backtrack chunk length (NCHUNK*CL = 512)

// Scratch (no cudaMalloc allowed). All [t][b]-major for coalesced lane access.
__device__ float4   g_emis[(TT+8)*BATCH];   // [t*64+b], +8 rows padding for prefetch overrun
__device__ float4   g_scores[TT*BATCH];     // [t*64+b] viterbi scores
__device__ unsigned g_map32[TT*BATCH];      // [s*64+b] byte-form backpointer map (s=0..510)
__device__ unsigned g_cmap[NCHUNK*BATCH];   // [c*64+b] chunk-composed map
__device__ int      g_btag[NCHUNK*BATCH];   // [c*64+b] incoming tag for chunk replay
__device__ int      g_best[BATCH];

// pack byte-form map (bytes 0..3, values 0..3) into a PRMT nibble selector
__device__ __forceinline__ unsigned nibsel(unsigned x) {
    unsigned y = x | (x >> 4);
    unsigned t = y & 0x00FF00FFu;
    return (t | (t >> 8)) & 0xFFFFu;
}

// ---------------------------------------------------------------------------
// K1: emissions[b,t,k] = sum_h sentences[b,t,h]*W[k,h] + bias[k]
// warp-per-row, W in shared, float4 coalesced, shuffle reduce. HBM-bound.
// Stores TRANSPOSED: g_emis[t*64 + b].
// ---------------------------------------------------------------------------
__global__ __launch_bounds__(256) void k_emissions(
    const float* __restrict__ sent,   // [B,T,H]
    const float* __restrict__ W,      // [K,H]
    const float* __restrict__ bias)   // [K]
{
    __shared__ float4 sW[KK][HH/4];   // 12 KB
    __shared__ float  sb[KK];
    int tid = threadIdx.x;

    const float4* W4 = (const float4*)W;
    for (int i = tid; i < KK*(HH/4); i += blockDim.x)
        sW[i/(HH/4)][i%(HH/4)] = W4[i];
    if (tid < KK) sb[tid] = bias[tid];
    __syncthreads();

    int warp = tid >> 5, lane = tid & 31;
    int row  = blockIdx.x * (blockDim.x >> 5) + warp;
    if (row >= ROWS) return;

    const float4* x = (const float4*)(sent + (size_t)row * HH);
    float a0 = 0.f, a1 = 0.f, a2 = 0.f, a3 = 0.f;
    #pragma unroll
    for (int i = 0; i < HH/128; i++) {            // 6 iterations
        int idx = i*32 + lane;
        float4 v  = x[idx];
        float4 w0 = sW[0][idx];
        float4 w1 = sW[1][idx];
        float4 w2 = sW[2][idx];
        float4 w3 = sW[3][idx];
        a0 += v.x*w0.x + v.y*w0.y + v.z*w0.z + v.w*w0.w;
        a1 += v.x*w1.x + v.y*w1.y + v.z*w1.z + v.w*w1.w;
        a2 += v.x*w2.x + v.y*w2.y + v.z*w2.z + v.w*w2.w;
        a3 += v.x*w3.x + v.y*w3.y + v.z*w3.z + v.w*w3.w;
    }
    #pragma unroll
    for (int d = 16; d; d >>= 1) {
        a0 += __shfl_xor_sync(0xffffffffu, a0, d);
        a1 += __shfl_xor_sync(0xffffffffu, a1, d);
        a2 += __shfl_xor_sync(0xffffffffu, a2, d);
        a3 += __shfl_xor_sync(0xffffffffu, a3, d);
    }
    if (lane == 0) {
        int b = row >> 9;            // row / TT
        int t = row & (TT-1);        // row % TT
        g_emis[t*BATCH + b] = make_float4(a0 + sb[0], a1 + sb[1], a2 + sb[2], a3 + sb[3]);
    }
}

// ---------------------------------------------------------------------------
// K2: Viterbi forward scan. thread = batch, one 64-thread block.
// Transposed emission loads (coalesced), unconditional 8-deep prefetch
// (padded array), peeled 7-step tail. Stores scores [t][b] for K3a.
// ---------------------------------------------------------------------------
__global__ __launch_bounds__(64) void k_forward(
    const float* __restrict__ startT,
    const float* __restrict__ endT,
    const float* __restrict__ trans)   // [K,K], trans[i*4+j]
{
    int b = threadIdx.x;                     // 0..63

    float T00=__ldg(trans+ 0), T01=__ldg(trans+ 1), T02=__ldg(trans+ 2), T03=__ldg(trans+ 3);
    float T10=__ldg(trans+ 4), T11=__ldg(trans+ 5), T12=__ldg(trans+ 6), T13=__ldg(trans+ 7);
    float T20=__ldg(trans+ 8), T21=__ldg(trans+ 9), T22=__ldg(trans+10), T23=__ldg(trans+11);
    float T30=__ldg(trans+12), T31=__ldg(trans+13), T32=__ldg(trans+14), T33=__ldg(trans+15);

    float4 e0 = g_emis[0*BATCH + b];
    float s0 = __ldg(startT+0) + e0.x;
    float s1 = __ldg(startT+1) + e0.y;
    float s2 = __ldg(startT+2) + e0.z;
    float s3 = __ldg(startT+3) + e0.w;
    g_scores[0*BATCH + b] = make_float4(s0, s1, s2, s3);

    float4 buf[8];
    #pragma unroll
    for (int j = 0; j < 8; j++) buf[j] = g_emis[(1 + j)*BATCH + b];

    // main: groups base = 1, 9, ..., 497  (t = 1..504), no predicates
    for (int base = 1; base <= 497; base += 8) {
        #pragma unroll
        for (int j = 0; j < 8; j++) {
            int t = base + j;
            float4 e = buf[j];
            buf[j] = g_emis[(t + 8)*BATCH + b];   // safe: padded to TT+8 rows

            float c0, c1, c2, c3, n0, n1, n2, n3;
            c0 = s0 + T00; c1 = s1 + T10; c2 = s2 + T20; c3 = s3 + T30;
            n0 = fmaxf(fmaxf(c0, c1), fmaxf(c2, c3)) + e.x;
            c0 = s0 + T01; c1 = s1 + T11; c2 = s2 + T21; c3 = s3 + T31;
            n1 = fmaxf(fmaxf(c0, c1), fmaxf(c2, c3)) + e.y;
            c0 = s0 + T02; c1 = s1 + T12; c2 = s2 + T22; c3 = s3 + T32;
            n2 = fmaxf(fmaxf(c0, c1), fmaxf(c2, c3)) + e.z;
            c0 = s0 + T03; c1 = s1 + T13; c2 = s2 + T23; c3 = s3 + T33;
            n3 = fmaxf(fmaxf(c0, c1), fmaxf(c2, c3)) + e.w;
            s0 = n0; s1 = n1; s2 = n2; s3 = n3;
            g_scores[t*BATCH + b] = make_float4(s0, s1, s2, s3);
        }
    }

    // tail: t = 505..511 (buf[j] holds em[505+j] after last group)
    #pragma unroll
    for (int j = 0; j < 7; j++) {
        int t = 505 + j;
        float4 e = buf[j];
        float c0, c1, c2, c3, n0, n1, n2, n3;
        c0 = s0 + T00; c1 = s1 + T10; c2 = s2 + T20; c3 = s3 + T30;
        n0 = fmaxf(fmaxf(c0, c1), fmaxf(c2, c3)) + e.x;
        c0 = s0 + T01; c1 = s1 + T11; c2 = s2 + T21; c3 = s3 + T31;
        n1 = fmaxf(fmaxf(c0, c1), fmaxf(c2, c3)) + e.y;
        c0 = s0 + T02; c1 = s1 + T12; c2 = s2 + T22; c3 = s3 + T32;
        n2 = fmaxf(fmaxf(c0, c1), fmaxf(c2, c3)) + e.z;
        c0 = s0 + T03; c1 = s1 + T13; c2 = s2 + T23; c3 = s3 + T33;
        n3 = fmaxf(fmaxf(c0, c1), fmaxf(c2, c3)) + e.w;
        s0 = n0; s1 = n1; s2 = n2; s3 = n3;
        g_scores[t*BATCH + b] = make_float4(s0, s1, s2, s3);
    }

    float f0 = s0 + __ldg(endT+0);
    float f1 = s1 + __ldg(endT+1);
    float f2 = s2 + __ldg(endT+2);
    float f3 = s3 + __ldg(endT+3);
    int best = 0; float m = f0;                 // first-index tie-break (strict >)
    if (f1 > m) { m = f1; best = 1; }
    if (f2 > m) { m = f2; best = 2; }
    if (f3 > m) { m = f3; best = 3; }
    g_best[b] = best;
}

// ---------------------------------------------------------------------------
// K3a: per (chunk c, batch b): compute per-step backpointer maps
//   f_s[j] = argmax_i ( scores[s][i] + trans[i][j] ), first-index wins,
// store them, and compose the chunk map F_c = f_{16c} o ... o f_{16c+15}
// (exact integer composition via PRMT; no fp reassociation anywhere).
// ---------------------------------------------------------------------------
__global__ __launch_bounds__(64) void k_chunk(const float* __restrict__ trans)
{
    int b = threadIdx.x;
    int c = blockIdx.x;
    int sbase = c * CL;
    int ns = (c == NCHUNK-1) ? (CL-1) : CL;   // chunk 31 covers s=496..510 (15 maps)

    float tr[16];
    #pragma unroll
    for (int i = 0; i < 16; i++) tr[i] = __ldg(trans + i);

    unsigned m[CL];
    #pragma unroll
    for (int k = 0; k < CL; k++) {
        if (k < ns) {
            float4 sc = g_scores[(sbase + k)*BATCH + b];
            unsigned h = 0;
            #pragma unroll
            for (int j = 0; j < 4; j++) {
                float c0 = sc.x + tr[0*4+j];
                float c1 = sc.y + tr[1*4+j];
                float c2 = sc.z + tr[2*4+j];
                float c3 = sc.w + tr[3*4+j];
                int bp = 0; float mm = c0;
                if (c1 > mm) { mm = c1; bp = 1; }
                if (c2 > mm) { mm = c2; bp = 2; }
                if (c3 > mm) { mm = c3; bp = 3; }
                h |= (unsigned)bp << (8*j);
            }
            m[k] = h;
            g_map32[(sbase + k)*BATCH + b] = h;
        }
    }

    // compose top-down: F = f_{sbase} o ... o f_{sbase+ns-1}
    unsigned F = m[ns-1];
    #pragma unroll
    for (int k = CL-2; k >= 0; k--)
        if (k <= ns-2)
            F = __byte_perm(m[k], 0, nibsel(F));
    g_cmap[c*BATCH + b] = F;
}

// ---------------------------------------------------------------------------
// K3b: suffix walk over chunk maps -> incoming tag per chunk; writes out[511].
// ---------------------------------------------------------------------------
__global__ __launch_bounds__(64) void k_btag(float* __restrict__ out)
{
    int b = threadIdx.x;
    unsigned Fs[NCHUNK];
    #pragma unroll
    for (int c = 0; c < NCHUNK; c++) Fs[c] = g_cmap[c*BATCH + b];

    int t = g_best[b];
    out[b*TT + (TT-1)] = (float)t;
    #pragma unroll
    for (int c = NCHUNK-1; c >= 0; c--) {
        g_btag[c*BATCH + b] = t;          // tag entering chunk c's replay
        t = __byte_perm(Fs[c], 0, t) & 3; // tag at chunk c's bottom boundary
    }
}

// ---------------------------------------------------------------------------
// K4: parallel chunk replay. thread (c,b): 16 PRMT steps, coalesced map loads.
// ---------------------------------------------------------------------------
__global__ __launch_bounds__(64) void k_replay(float* __restrict__ out)
{
    int b = threadIdx.x;
    int c = blockIdx.x;
    int sbase = c * CL;
    int ns = (c == NCHUNK-1) ? (CL-1) : CL;

    unsigned m[CL];
    #pragma unroll
    for (int k = 0; k < CL; k++)
        if (k < ns) m[k] = g_map32[(sbase + k)*BATCH + b];

    int tag = g_btag[c*BATCH + b];
    #pragma unroll
    for (int k = CL-1; k >= 0; k--) {
        if (k < ns) {
            tag = __byte_perm(m[k], 0, tag) & 3;
            out[b*TT + sbase + k] = (float)tag;
        }
    }
}

// ---------------------------------------------------------------------------
// Bind inputs BY ELEMENT COUNT (robust to input-order permutation).
// The three 4-element vectors keep their relative order: b, start, end.
// __output__ dtype is float32 (established R7).
// ---------------------------------------------------------------------------
extern "C" void kernel_launch(void* const* d_in, const int* in_sizes, int n_in,
                              void* d_out, int out_size)
{
    const float* sent   = 0;
    const float* W      = 0;
    const float* bias   = 0;
    const float* startT = 0;
    const float* endT   = 0;
    const float* trans  = 0;

    int n4 = 0;
    for (int i = 0; i < n_in; i++) {
        int sz = in_sizes[i];
        const float* p = (const float*)d_in[i];
        if      (sz == BATCH*TT*HH) sent  = p;
        else if (sz == KK*HH)       W     = p;
        else if (sz == KK*KK)       trans = p;
        else if (sz == KK) {
            if      (n4 == 0) bias   = p;
            else if (n4 == 1) startT = p;
            else              endT   = p;
            n4++;
        }
    }
    float* out = (float*)d_out;                   // [64,512] float32

    k_emissions<<<ROWS/8, 256>>>(sent, W, bias);
    k_forward<<<1, 64>>>(startT, endT, trans);
    k_chunk<<<NCHUNK, 64>>>(trans);
    k_btag<<<1, 64>>>(out);
    k_replay<<<NCHUNK, 64>>>(out);
}